// round 15
// baseline (speedup 1.0000x reference)
#include <cuda_runtime.h>
#include <math.h>

#define T_DATA 40000
#define SUB    32
#define EE     2000
#define EI     400
#define TAPS   200
#define NCOS   17
#define CBT    2048   // conv tile (outputs per block), 256 thr * 8
#define VBT    512    // vconv tile

// padded smem index for conv: conflict-free LDS.64
#define PX(i) ((i) + ((i) >> 3))

// ---------------- device scratch (no allocations allowed) ----------------
__device__ float  g_syn_e[SUB * T_DATA];
__device__ float  g_syn_i[SUB * T_DATA];
__device__ float  g_syn[(SUB + 1) * T_DATA];   // ch 0..31 subunit drive, ch 32 = hist_filt
__device__ float  g_zout[T_DATA];
__device__ float  g_ek[SUB * TAPS];
__device__ float  g_ik[SUB * TAPS];
__device__ float  g_hk[TAPS];
__device__ float  g_ok[TAPS];
__device__ int    g_ntap[SUB + 1];             // adaptive per-channel tap count (mult of 8)
__device__ float  g_cwj[SUB + 1];              // weight for child j (binary tree), [32]=0
__device__ float2 g_lut_e[EE];                 // (weight, bitcast subunit*4 byte-offset)
__device__ float2 g_lut_i[EI];

// ---------------- f32x2 helpers (sm_103a packed fp32) ----------------
__device__ __forceinline__ unsigned long long pk2(float2 v) {
    unsigned long long r;
    asm("mov.b64 %0, {%1, %2};" : "=l"(r) : "f"(v.x), "f"(v.y));
    return r;
}
__device__ __forceinline__ void fma2(unsigned long long& d, unsigned long long a,
                                     unsigned long long b) {
    asm("fma.rn.f32x2 %0, %1, %2, %0;" : "+l"(d) : "l"(a), "l"(b));
}
__device__ __forceinline__ float unpk_sum(unsigned long long v) {
    float lo, hi;
    asm("mov.b64 {%0, %1}, %2;" : "=f"(lo), "=f"(hi) : "l"(v));
    return lo + hi;
}

// branchless fast tanh: MUFU EX2 + MUFU RCP. |err| ~1e-6.
__device__ __forceinline__ float tanh_b(float x) {
    float e = __expf(-2.0f * fabsf(x));
    float r = __fdividef(1.0f - e, 1.0f + e);
    return copysignf(r, x);
}

// predicated shared-mem reduction: no BSSY/BSYNC
__device__ __forceinline__ void red_if(unsigned accBase, float2 p, float v) {
    unsigned addr = accBase + (unsigned)__float_as_int(p.y);  // p.y = byte offset
    asm volatile(
        "{\n\t"
        ".reg .pred q;\n\t"
        "setp.ne.f32 q, %0, 0f00000000;\n\t"
        "@q red.shared.add.f32 [%1], %2;\n\t"
        "}"
        :: "f"(v), "r"(addr), "f"(v * p.x) : "memory");
}

__device__ __forceinline__ float alpha_k(float u, float delta, float tau, float w,
                                         float sgn) {
    float t = fmaxf(u - expf(delta), 0.f);
    float tt = t / expf(tau);
    return sgn * tt * expf(-tt) * expf(w);
}

// branch-free zero of a float4 when !keep (FSEL, no BSSY)
__device__ __forceinline__ float4 sel4(float4 v, bool keep) {
    float m = keep ? 1.f : 0.f;
    return make_float4(v.x * m, v.y * m, v.z * m, v.w * m);
}

// ---------------- K0: prep (grid-parallel) ----------------
__global__ void prep_kernel(const float* __restrict__ C_den,
                            const float* __restrict__ Cse,
                            const float* __restrict__ Csi,
                            const float* __restrict__ Tau,
                            const float* __restrict__ Delta,
                            const float* __restrict__ Wsyn,
                            const float* __restrict__ Wsub,
                            const float* __restrict__ Whist,
                            const float* __restrict__ TauOut,
                            const float* __restrict__ Wout,
                            float* __restrict__ d_out, int out_size) {
    const int gtid = blockIdx.x * blockDim.x + threadIdx.x;
    const int gsz  = gridDim.x * blockDim.x;

    for (int e = gtid; e < EE; e += gsz) {
        int s0 = 0; float w = 0.f;
        for (int s = 0; s < SUB; s++) {
            float c = Cse[s * EE + e];
            if (c != 0.f) { s0 = s; w = c; }
        }
        g_lut_e[e] = make_float2(w, __int_as_float(s0 * 4));
    }
    for (int e = gtid; e < EI; e += gsz) {
        int s0 = 0; float w = 0.f;
        for (int s = 0; s < SUB; s++) {
            float c = Csi[s * EI + e];
            if (c != 0.f) { s0 = s; w = c; }
        }
        g_lut_i[e] = make_float2(w, __int_as_float(s0 * 4));
    }

    for (int idx = gtid; idx < SUB * TAPS; idx += gsz) {
        const int s = idx / TAPS, u = idx % TAPS;
        const float tf = (float)u;
        float ek = alpha_k(tf, Delta[s * 2 + 0], Tau[s * 2 + 0], Wsyn[s * 2 + 0],  1.f);
        float ik = alpha_k(tf, Delta[s * 2 + 1], Tau[s * 2 + 1], Wsyn[s * 2 + 1], -1.f);
        g_ek[idx] = ek;
        g_ik[idx] = ik;
        const int base = 2 * T_DATA;
        if (base + idx < out_size)              d_out[base + idx] = ek;
        if (base + SUB * TAPS + idx < out_size) d_out[base + SUB * TAPS + idx] = ik;
    }

    for (int u = gtid; u < TAPS; u += gsz) {
        const float raw = 4.0f * logf((float)u + 1.0f);
        const float pi_f    = 3.14159274101257324f;
        const float half_pi = 1.57079637050628662f;
        float hk = 0.f;
        for (int n = 0; n < NCOS; n++) {
            float phi = half_pi * (float)n;
            float b = 0.f;
            if (raw >= phi - pi_f && raw <= phi + pi_f)
                b = 0.5f * cosf(raw - phi) + 0.5f;
            hk -= expf(Whist[n]) * b;
        }
        g_hk[u] = hk;
        const int base = 2 * T_DATA + 2 * SUB * TAPS;
        if (base + u < out_size) d_out[base + u] = hk;
    }

    for (int u = gtid; u < TAPS; u += gsz) {
        float tto = (float)u / expf(TauOut[0]);
        g_ok[u] = tto * expf(-tto) * expf(Wout[0]);
    }

    if (gtid >= 1 && gtid < SUB)
        g_cwj[gtid] = C_den[((gtid - 1) >> 1) * SUB + gtid] * expf(Wsub[gtid]);
    if (gtid == 0) { g_cwj[0] = 0.f; g_cwj[SUB] = 0.f; }

    // adaptive tap counts (block 0 only)
    if (blockIdx.x == 0) {
        __shared__ float sk[(SUB + 1) * TAPS];
        const int tid = threadIdx.x;
        for (int idx = tid; idx < SUB * TAPS; idx += blockDim.x) {
            const int s = idx / TAPS, u = idx % TAPS;
            const float tf = (float)u;
            float ek = alpha_k(tf, Delta[s * 2 + 0], Tau[s * 2 + 0], Wsyn[s * 2 + 0], 1.f);
            float ik = alpha_k(tf, Delta[s * 2 + 1], Tau[s * 2 + 1], Wsyn[s * 2 + 1], 1.f);
            sk[idx] = fabsf(ek) + fabsf(ik);
        }
        for (int u = tid; u < TAPS; u += blockDim.x) {
            const float raw = 4.0f * logf((float)u + 1.0f);
            const float pi_f    = 3.14159274101257324f;
            const float half_pi = 1.57079637050628662f;
            float hk = 0.f;
            for (int n = 0; n < NCOS; n++) {
                float phi = half_pi * (float)n;
                float b = 0.f;
                if (raw >= phi - pi_f && raw <= phi + pi_f)
                    b = 0.5f * cosf(raw - phi) + 0.5f;
                hk -= expf(Whist[n]) * b;
            }
            sk[SUB * TAPS + u] = fabsf(hk);
        }
        __syncthreads();
        if (tid < SUB + 1) {
            const float* k = sk + tid * TAPS;
            float mx = 0.f;
            for (int u = 0; u < TAPS; u++) mx = fmaxf(mx, k[u]);
            const float thr = mx * 1e-9f;
            int last = 0;
            for (int u = 0; u < TAPS; u++)
                if (k[u] > thr) last = u;
            int U = ((last + 8) / 8) * 8;
            if (U < 8) U = 8;
            if (U > TAPS) U = TAPS;
            g_ntap[tid] = U;
        }
    }
}

// ---------------- K1: spike projection — 4-deep prefetch + predicated RED ----------
#define PBT 16  // timesteps per block
#define EROW (EE / 4)         // 500
#define IROW (EI / 4)         // 100
#define EITER (EROW / 32 + 1) // 16 iterations (last partial)
__global__ void proj_kernel(const float* __restrict__ Se, const float* __restrict__ Si) {
    // LUTs padded to pow2: tail OOB indices stay in-bounds (v==0 -> red pred-off)
    __shared__ float2 lutE[4][512];
    __shared__ float2 lutI[4][128];
    __shared__ float  acc_e[PBT][SUB + 1];
    __shared__ float  acc_i[PBT][SUB + 1];
    const int tid  = threadIdx.x;
    const int wid  = tid >> 5;
    const int lane = tid & 31;

    for (int c = tid; c < EE; c += 256) lutE[c & 3][c >> 2] = g_lut_e[c];
    for (int c = tid; c < EI; c += 256) lutI[c & 3][c >> 2] = g_lut_i[c];
    for (int i = tid; i < PBT * (SUB + 1); i += 256) {
        (&acc_e[0][0])[i] = 0.f;
        (&acc_i[0][0])[i] = 0.f;
    }
    __syncthreads();

    const int t0 = blockIdx.x * PBT;
    const float4* Se4 = reinterpret_cast<const float4*>(Se);
    const float4* Si4 = reinterpret_cast<const float4*>(Si);

    #pragma unroll
    for (int rr = 0; rr < 2; rr++) {
        const int tl = wid * 2 + rr;
        {   // ---- excitatory row: 4-deep ring prefetch (READ slot, THEN refill) ----
            const float4* rowE = Se4 + (size_t)(t0 + tl) * EROW;
            const unsigned accE = (unsigned)__cvta_generic_to_shared(acc_e[tl]);
            float4 buf[4];
            #pragma unroll
            for (int p = 0; p < 4; p++)
                buf[p] = rowE[lane + 32 * p];           // lane+96 <= 127 < 500: valid
            #pragma unroll
            for (int k = 0; k < EITER; k++) {
                const float4 cur = buf[k & 3];          // consume slot FIRST
                if (k + 4 < EITER) {                    // then refill it for k+4
                    const int nidx = lane + 32 * (k + 4);
                    float4 t4 = rowE[nidx < EROW ? nidx : EROW - 1];
                    buf[k & 3] = sel4(t4, nidx < EROW);
                }
                const int c4 = lane + 32 * k;
                red_if(accE, lutE[0][c4], cur.x);
                red_if(accE, lutE[1][c4], cur.y);
                red_if(accE, lutE[2][c4], cur.z);
                red_if(accE, lutE[3][c4], cur.w);
            }
        }
        {   // ---- inhibitory row: whole row fits in the 4-deep buffer ----
            const float4* rowI = Si4 + (size_t)(t0 + tl) * IROW;
            const unsigned accI = (unsigned)__cvta_generic_to_shared(acc_i[tl]);
            float4 buf[4];
            #pragma unroll
            for (int p = 0; p < 4; p++) {
                const int idx = lane + 32 * p;
                float4 t4 = rowI[idx < IROW ? idx : IROW - 1];
                buf[p] = sel4(t4, idx < IROW);
            }
            #pragma unroll
            for (int k = 0; k < 4; k++) {
                const float4 cur = buf[k];
                const int c4 = lane + 32 * k;
                red_if(accI, lutI[0][c4], cur.x);
                red_if(accI, lutI[1][c4], cur.y);
                red_if(accI, lutI[2][c4], cur.z);
                red_if(accI, lutI[3][c4], cur.w);
            }
        }
    }
    __syncthreads();

    for (int idx = tid; idx < SUB * PBT; idx += 256) {
        const int s = idx / PBT, tl = idx % PBT;
        g_syn_e[s * T_DATA + t0 + tl] = acc_e[tl][s];
        g_syn_i[s * T_DATA + t0 + tl] = acc_i[tl][s];
    }
}

// ---------------- K2: 33-ch causal conv, adaptive tap count ----------
__global__ void conv_kernel(const float* __restrict__ Z) {
    __shared__ float2 sig[PX(CBT + TAPS - 1) + 2];
    __shared__ float2 kk[TAPS];
    const int ch  = blockIdx.y;
    const int t0  = blockIdx.x * CBT;
    const int tid = threadIdx.x;
    const bool has_i = (ch < SUB);

    const float* pe = has_i ? (g_syn_e + ch * T_DATA) : Z;
    const float* pi = has_i ? (g_syn_i + ch * T_DATA) : nullptr;
    const float* ke = has_i ? (g_ek + ch * TAPS) : g_hk;
    const float* ki = has_i ? (g_ik + ch * TAPS) : nullptr;
    const int ntap = g_ntap[ch];

    for (int i = tid; i < CBT + TAPS; i += 256) {
        const int t = t0 - TAPS + i;
        const bool ok = (t >= 0) && (t < T_DATA);
        float a = ok ? pe[t] : 0.f;
        float b = (ok && has_i) ? pi[t] : 0.f;
        sig[PX(i)] = make_float2(a, b);
    }
    for (int u = tid; u < TAPS; u += 256)
        kk[u] = make_float2(ke[u], has_i ? ki[u] : 0.f);
    __syncthreads();

    const int base = tid * 8;
    unsigned long long acc[8];
    unsigned long long w[8];
    #pragma unroll
    for (int r = 0; r < 8; r++) acc[r] = 0ull;
    #pragma unroll
    for (int r = 0; r < 8; r++) w[(7 + r) & 7] = pk2(sig[PX(base + 199 + r)]);

    for (int g = 0; g < ntap; g += 8) {
        #pragma unroll
        for (int c = 0; c < 8; c++) {
            const int u = g + c;
            if (u > 0) w[(7 - c) & 7] = pk2(sig[PX(base + 199 - u)]);
            const unsigned long long k2 = pk2(kk[u]);
            #pragma unroll
            for (int r = 0; r < 8; r++)
                fma2(acc[r], k2, w[(7 - c + r) & 7]);
        }
    }

    #pragma unroll
    for (int r = 0; r < 8; r++) {
        const int t = t0 + base + r;
        if (t < T_DATA) g_syn[ch * T_DATA + t] = unpk_sum(acc[r]);
    }
}

// ---------------- K3: tree walk — static topology, 1 sample/thread (R12-best) ------
__global__ void tree_kernel(const float* __restrict__ Theta,
                            float* __restrict__ d_out, int out_size) {
    __shared__ float th[SUB];
    __shared__ float cw[SUB + 1];      // cw[32] = 0
    const int tid = threadIdx.x;
    if (tid < SUB) th[tid] = Theta[tid];
    if (tid < SUB + 1) cw[tid] = g_cwj[tid];
    __syncthreads();

    const int t = blockIdx.x * 256 + tid;
    if (t >= T_DATA) return;

    float v[SUB + 1];
    #pragma unroll
    for (int s = 0; s < SUB; s++) v[s] = g_syn[s * T_DATA + t];
    v[SUB] = 0.f;
    const float hist = g_syn[SUB * T_DATA + t];

    // leaves (no children)
    #pragma unroll
    for (int i = 16; i < SUB; i++) v[i] = tanh_b(v[i] + th[i]);
    // internal nodes: children 2i+1, 2i+2 (i=15 uses v[32]=0, cw[32]=0)
    #pragma unroll
    for (int i = 15; i >= 1; i--) {
        float a = v[i] + th[i];
        a = fmaf(cw[2 * i + 1], v[2 * i + 1], a);
        a = fmaf(cw[2 * i + 2], v[2 * i + 2], a);
        v[i] = tanh_b(a);
    }

    float zin = hist + v[0] + th[0];
    zin = fmaf(cw[1], v[1], zin);
    zin = fmaf(cw[2], v[2], zin);

    const float zo = (zin > 0.f) ? 1.f : 0.f;
    g_zout[t] = zo;
    if (T_DATA + t < out_size) d_out[T_DATA + t] = zo;
}

// ---------------- K4: output alpha-kernel conv of Z_out -> V_out ------------------
__global__ void vconv_kernel(float* __restrict__ d_out, int out_size) {
    __shared__ float sig[VBT + TAPS];
    __shared__ float kern[TAPS];
    const int t0  = blockIdx.x * VBT;
    const int tid = threadIdx.x;
    for (int i = tid; i < VBT + TAPS; i += 256) {
        const int t = t0 - TAPS + i;
        sig[i] = (t >= 0 && t < T_DATA) ? g_zout[t] : 0.f;
    }
    for (int u = tid; u < TAPS; u += 256) kern[u] = g_ok[u];
    __syncthreads();

    float a0 = 0.f, a1 = 0.f;
    for (int u = 0; u < TAPS; u++) {
        const float k = kern[u];
        a0 = fmaf(k, sig[tid + 199 - u], a0);
        a1 = fmaf(k, sig[tid + 256 + 199 - u], a1);
    }
    int t = t0 + tid;
    if (t < T_DATA && t < out_size) d_out[t] = a0;
    t += 256;
    if (t < T_DATA && t < out_size) d_out[t] = a1;
}

// ---------------- launch ----------------
extern "C" void kernel_launch(void* const* d_in, const int* in_sizes, int n_in,
                              void* d_out, int out_size) {
    const float* S_e    = (const float*)d_in[0];
    const float* S_i    = (const float*)d_in[1];
    const float* Z      = (const float*)d_in[2];
    const float* C_den  = (const float*)d_in[3];
    const float* Cse    = (const float*)d_in[4];
    const float* Csi    = (const float*)d_in[5];
    const float* Tau    = (const float*)d_in[6];
    const float* Delta  = (const float*)d_in[7];
    const float* Wsyn   = (const float*)d_in[8];
    const float* Wsub   = (const float*)d_in[9];
    const float* Whist  = (const float*)d_in[10];
    const float* Theta  = (const float*)d_in[11];
    const float* TauOut = (const float*)d_in[12];
    const float* Wout   = (const float*)d_in[13];
    float* out = (float*)d_out;

    prep_kernel<<<64, 256>>>(C_den, Cse, Csi, Tau, Delta, Wsyn, Wsub, Whist,
                             TauOut, Wout, out, out_size);
    proj_kernel<<<T_DATA / PBT, 256>>>(S_e, S_i);
    const int ctiles = (T_DATA + CBT - 1) / CBT;  // 20
    conv_kernel<<<dim3(ctiles, SUB + 1), 256>>>(Z);
    tree_kernel<<<(T_DATA + 255) / 256, 256>>>(Theta, out, out_size);
    vconv_kernel<<<(T_DATA + VBT - 1) / VBT, 256>>>(out, out_size);
}